// round 11
// baseline (speedup 1.0000x reference)
#include <cuda_runtime.h>

#define BATCH   8
#define NNODE   256
#define XHIN    9
#define XHHID   64
#define POSHID  192
#define TWO_PI_F 6.283185307179586f
#define NTILE   8      // 256 / 32
#define NPAIR   36     // NTILE*(NTILE+1)/2

// Partial PE sums: [batch][slot][row][freq], freq = [sin 0..63, cos 64..127].
// Row in row-tile T gets j-side partials in slots 0..T-1 and i-side partials
// in slots T..7 -> all 8 slots covered exactly once => no atomics, no init.
__device__ float g_Spart[BATCH][NTILE][NNODE][128];

// ---------------------------------------------------------------------------
// Pair kernel (unchanged, near its MUFU floor): one block per (batch,
// upper-tri 32x32 tile-pair). Off-diag pairs computed once, both sides.
// grid = 288, block = 256
// ---------------------------------------------------------------------------
__global__ __launch_bounds__(256) void pair_kernel(
    const float* __restrict__ xh,
    const float* __restrict__ node_mask)
{
    int b = blockIdx.x / NPAIR;
    int p = blockIdx.x % NPAIR;
    int ti = 0, rem = p;
    while (rem >= NTILE - ti) { rem -= NTILE - ti; ti++; }
    int tj = ti + rem;
    bool offdiag = (ti != tj);

    int t = threadIdx.x;
    int w = t >> 5, l = t & 31;
    int r = w & 3;
    int g = w >> 2;

    __shared__ float  xi[3][32], xj[3][32];
    __shared__ float  mi_sm[32], mj_sm[32];
    __shared__ float  a_sm[32 * 32];
    __shared__ float2 SjP[8][16][32];

    if (t < 32) {
        int rowg = b * NNODE + ti * 32 + t;
        xi[0][t] = xh[rowg * XHIN + 0];
        xi[1][t] = xh[rowg * XHIN + 1];
        xi[2][t] = xh[rowg * XHIN + 2];
        mi_sm[t] = node_mask[rowg];
    } else if (t < 64) {
        int tt = t - 32;
        int rowg = b * NNODE + tj * 32 + tt;
        xj[0][tt] = xh[rowg * XHIN + 0];
        xj[1][tt] = xh[rowg * XHIN + 1];
        xj[2][tt] = xh[rowg * XHIN + 2];
        mj_sm[tt] = node_mask[rowg];
    }
    __syncthreads();

    #pragma unroll
    for (int k = 0; k < 4; k++) {
        int q = t + k * 256;
        int i = q & 31, j = q >> 5;
        float dx = xi[0][i] - xj[0][j];
        float dy = xi[1][i] - xj[1][j];
        float dz = xi[2][i] - xj[2][j];
        float sq = fmaxf(fmaf(dx, dx, fmaf(dy, dy, dz * dz)), 0.0f);
        a_sm[j * 32 + i] = TWO_PI_F * sqrtf(sq + 1e-12f);
    }
    __syncthreads();

    const float c1 = 0.10381025296522944f;           // log2(100)/64
    float f = exp2f((float)(g * 32 + l) * c1);

    float mi[8];
    #pragma unroll
    for (int k = 0; k < 8; k++) mi[k] = mi_sm[r * 8 + k];

    float ssA[8], ccA[8];
    #pragma unroll
    for (int k = 0; k < 8; k++) { ssA[k] = 0.f; ccA[k] = 0.f; }

    for (int h = 0; h < 2; h++) {
        #pragma unroll 4
        for (int j2 = 0; j2 < 16; j2++) {
            int j = h * 16 + j2;
            float mj = mj_sm[j];
            const float4* ap = (const float4*)&a_sm[j * 32 + r * 8];
            float4 a0 = ap[0];
            float4 a1 = ap[1];
            float av[8] = {a0.x, a0.y, a0.z, a0.w, a1.x, a1.y, a1.z, a1.w};
            float sjs = 0.f, sjc = 0.f;
            #pragma unroll
            for (int k = 0; k < 8; k++) {
                float ang = av[k] * f;
                float s = __sinf(ang);
                float c = __cosf(ang);
                ssA[k] = fmaf(mj, s, ssA[k]);
                ccA[k] = fmaf(mj, c, ccA[k]);
                sjs    = fmaf(mi[k], s, sjs);
                sjc    = fmaf(mi[k], c, sjc);
            }
            if (offdiag) SjP[w][j2][l] = make_float2(sjs, sjc);
        }

        if (offdiag) {
            __syncthreads();
            #pragma unroll
            for (int k = 0; k < 4; k++) {
                int idx = t + k * 256;
                int gg  = idx >> 9;
                int jj  = (idx >> 5) & 15;
                int ll  = idx & 31;
                float2 v0 = SjP[gg * 4 + 0][jj][ll];
                float2 v1 = SjP[gg * 4 + 1][jj][ll];
                float2 v2 = SjP[gg * 4 + 2][jj][ll];
                float2 v3 = SjP[gg * 4 + 3][jj][ll];
                float ss = (v0.x + v1.x) + (v2.x + v3.x);
                float cc = (v0.y + v1.y) + (v2.y + v3.y);
                float* rp = &g_Spart[b][ti][tj * 32 + h * 16 + jj][0];
                rp[gg * 32 + ll]      = ss;
                rp[64 + gg * 32 + ll] = cc;
            }
            __syncthreads();
        }
    }

    float* basei = &g_Spart[b][tj][ti * 32][0];
    #pragma unroll
    for (int k = 0; k < 8; k++) {
        float* rp = basei + (r * 8 + k) * 128;
        rp[g * 32 + l]      = ssA[k];
        rp[64 + g * 32 + l] = ccA[k];
    }
}

// ---------------------------------------------------------------------------
// Epilogue v4: 2-D tiled projection. grid = 128 row-groups (16 rows) x 4
// col-slices (48 cols) = 512 blocks -> ~3.5 blocks/SM (28 warps) for latency
// hiding, each staging only its 24KB W_pos slice (12.5MB chip traffic).
// Matvec: thread=(col,row-quad), 4 accs: LDS.128(S)+LDS(wv)+4FMA per k.
// Col-slice 3 additionally computes the masked mean and the 9->64 embedding
// using the 64 spare threads.
// grid = 512, block = 256, static smem ~37KB
// ---------------------------------------------------------------------------
__global__ __launch_bounds__(256) void ep_ditemb(
    const float* __restrict__ xh,
    const float* __restrict__ node_mask,
    const float* __restrict__ W_xh,
    const float* __restrict__ b_xh,
    const float* __restrict__ W_pos,
    const float* __restrict__ b_pos,
    float* __restrict__ out)
{
    int cb = blockIdx.x & 3;             // col slice: cols cb*48 .. cb*48+47
    int rg = blockIdx.x >> 2;            // row group
    int b  = rg >> 4;
    int i0 = (rg & 15) << 4;             // 16 rows
    int t  = threadIdx.x;
    int w  = t >> 5, l = t & 31;

    __shared__ float  sWp[128 * 48];     // W_pos slice, 24 KB
    __shared__ float4 S4[128][4];        // S [k][row-quad], 8 KB
    __shared__ float  mk[NNODE];
    __shared__ float  wred[8][4];
    __shared__ float  mean_s[3];
    __shared__ float  sc[2];             // [0]=1/N, [1]=256/N
    __shared__ float  xc16[16][3];
    __shared__ float  hs[16][6];
    __shared__ float  sW[XHIN * XHHID];
    __shared__ float  sB[XHHID];

    // -- stage W_pos slice: 6 independent LDG.128 per thread -----------------
    {
        float4*       dst = (float4*)sWp;
        const float4* src = (const float4*)W_pos;   // 192 floats = 48 float4/row
        #pragma unroll
        for (int ii = 0; ii < 6; ii++) {
            int idx = t + (ii << 8);                // 0..1535
            int row = idx / 12, c4 = idx % 12;
            dst[row * 12 + c4] = src[row * 48 + cb * 12 + c4];
        }
    }

    // -- slot sums: 8 values per thread, 64 independent coalesced LDG --------
    float ssum[8];
    #pragma unroll
    for (int k = 0; k < 8; k++) {
        int v = t + (k << 8);
        int rv = v >> 7, fv = v & 127;
        float s = 0.f;
        #pragma unroll
        for (int slot = 0; slot < NTILE; slot++)
            s += g_Spart[b][slot][i0 + rv][fv];
        ssum[k] = s;
    }

    // -- masks + reduction (N always; full mean only used by cb==3) ----------
    int row = b * NNODE + t;
    float m  = node_mask[row];
    float x0 = xh[row * XHIN + 0];
    float x1 = xh[row * XHIN + 1];
    float x2 = xh[row * XHIN + 2];
    mk[t] = m;

    float p0 = x0 * m, p1 = x1 * m, p2 = x2 * m, p3 = m;
    #pragma unroll
    for (int off = 16; off > 0; off >>= 1) {
        p0 += __shfl_down_sync(0xffffffffu, p0, off);
        p1 += __shfl_down_sync(0xffffffffu, p1, off);
        p2 += __shfl_down_sync(0xffffffffu, p2, off);
        p3 += __shfl_down_sync(0xffffffffu, p3, off);
    }
    if (l == 0) { wred[w][0] = p0; wred[w][1] = p1; wred[w][2] = p2; wred[w][3] = p3; }

    if (cb == 3) {
        for (int i = t; i < XHIN * XHHID; i += 256) sW[i] = W_xh[i];
        if (t < XHHID) sB[t] = b_xh[t];
        if (t < 96) {
            int rr = t / 6, cc = t % 6;
            hs[rr][cc] = xh[(size_t)(b * NNODE + i0 + rr) * XHIN + 3 + cc];
        }
    }
    __syncthreads();

    if (t < 4) {
        float s = wred[0][t] + wred[1][t] + wred[2][t] + wred[3][t]
                + wred[4][t] + wred[5][t] + wred[6][t] + wred[7][t];
        wred[0][t] = s;
    }
    __syncthreads();
    if (t < 3) mean_s[t] = wred[0][t] / wred[0][3];
    if (t == 0) {
        float Ns = wred[0][3];
        sc[0] = 1.0f / Ns;
        sc[1] = 256.0f / Ns;
    }
    __syncthreads();

    if (cb == 3 && t >= i0 && t < i0 + 16) {
        int k = t - i0;
        xc16[k][0] = (x0 - mean_s[0]) * m;
        xc16[k][1] = (x1 - mean_s[1]) * m;
        xc16[k][2] = (x2 - mean_s[2]) * m;
    }

    // -- finalize S = slotsum * mask_i / N, layout [k][row 0..15] ------------
    {
        float* Ssc = (float*)S4;
        float invN = sc[0];
        #pragma unroll
        for (int k = 0; k < 8; k++) {
            int v = t + (k << 8);
            int rv = v >> 7, fv = v & 127;
            Ssc[fv * 16 + rv] = ssum[k] * mk[i0 + rv] * invN;
        }
    }
    __syncthreads();

    if (t < POSHID) {
        // -- matvec: thread = (col c, row-quad rh) ---------------------------
        int c  = t % 48;
        int rh = t / 48;                 // 0..3 -> rows rh*4 .. rh*4+3
        float acc0 = 0.f, acc1 = 0.f, acc2 = 0.f, acc3 = 0.f;
        #pragma unroll 8
        for (int k = 0; k < 128; k++) {
            float4 sv = S4[k][rh];
            float  wv = sWp[k * 48 + c];
            acc0 = fmaf(sv.x, wv, acc0);
            acc1 = fmaf(sv.y, wv, acc1);
            acc2 = fmaf(sv.z, wv, acc2);
            acc3 = fmaf(sv.w, wv, acc3);
        }
        int col = cb * 48 + c;
        float bp = b_pos[col] * sc[1];
        int rbase = i0 + rh * 4;
        size_t obase = ((size_t)(b * NNODE + rbase)) * 256 + 64 + col;
        out[obase]           = (acc0 + bp) * mk[rbase + 0];
        out[obase + 256]     = (acc1 + bp) * mk[rbase + 1];
        out[obase + 512]     = (acc2 + bp) * mk[rbase + 2];
        out[obase + 768]     = (acc3 + bp) * mk[rbase + 3];
    } else if (cb == 3) {
        // -- xh embedding: 64 threads x 16 outputs (16 rows x 64 cols) -------
        int tt = t - POSHID;
        #pragma unroll
        for (int e = 0; e < 16; e++) {
            int v = tt * 16 + e;                 // 0..1023
            int r = v >> 6, o = v & 63;
            float mr = mk[i0 + r];
            float acc = sB[o];
            acc = fmaf(xc16[r][0], sW[0 * XHHID + o], acc);
            acc = fmaf(xc16[r][1], sW[1 * XHHID + o], acc);
            acc = fmaf(xc16[r][2], sW[2 * XHHID + o], acc);
            acc = fmaf(hs[r][0],   sW[3 * XHHID + o], acc);
            acc = fmaf(hs[r][1],   sW[4 * XHHID + o], acc);
            acc = fmaf(hs[r][2],   sW[5 * XHHID + o], acc);
            acc = fmaf(hs[r][3],   sW[6 * XHHID + o], acc);
            acc = fmaf(hs[r][4],   sW[7 * XHHID + o], acc);
            acc = fmaf(hs[r][5],   sW[8 * XHHID + o], acc);
            out[(size_t)(b * NNODE + i0 + r) * 256 + o] = acc * mr;
        }
    }
}

extern "C" void kernel_launch(void* const* d_in, const int* in_sizes, int n_in,
                              void* d_out, int out_size)
{
    // inputs (metadata order): t, xh, node_mask, edge_mask, W_xh, b_xh, W_pos, b_pos
    const float* xh        = (const float*)d_in[1];
    const float* node_mask = (const float*)d_in[2];
    const float* W_xh      = (const float*)d_in[4];
    const float* b_xh      = (const float*)d_in[5];
    const float* W_pos     = (const float*)d_in[6];
    const float* b_pos     = (const float*)d_in[7];
    float* out = (float*)d_out;

    pair_kernel<<<BATCH * NPAIR, 256>>>(xh, node_mask);
    ep_ditemb<<<512, 256>>>(xh, node_mask, W_xh, b_xh, W_pos, b_pos, out);
}

// round 12
// speedup vs baseline: 1.3282x; 1.3282x over previous
#include <cuda_runtime.h>

#define BATCH   8
#define NNODE   256
#define XHIN    9
#define XHHID   64
#define POSHID  192
#define TWO_PI_F 6.283185307179586f
#define NTILE   8      // 256 / 32
#define NPAIR   36     // NTILE*(NTILE+1)/2

// Partial PE sums: [batch][slot][row][freq], freq = [sin 0..63, cos 64..127].
// Row in row-tile T gets j-side partials in slots 0..T-1 and i-side partials
// in slots T..7 -> all 8 slots covered exactly once => no atomics, no init.
__device__ float g_Spart[BATCH][NTILE][NNODE][128];

// ---------------------------------------------------------------------------
// Pair kernel: one block per (batch, upper-tri 32x32 tile-pair).
// Off-diag pairs computed once, contribute to both row sums.
// DIAGONAL blocks (ti==tj, one per 32-row tile) additionally compute the
// batch masked mean + the 9->64 xh embedding for their 32 rows (they have
// slack: no j-side flush / barriers).
// grid = 288, block = 256
// ---------------------------------------------------------------------------
__global__ __launch_bounds__(256) void pair_kernel(
    const float* __restrict__ xh,
    const float* __restrict__ node_mask,
    const float* __restrict__ W_xh,
    const float* __restrict__ b_xh,
    float* __restrict__ out)
{
    int b = blockIdx.x / NPAIR;
    int p = blockIdx.x % NPAIR;
    int ti = 0, rem = p;
    while (rem >= NTILE - ti) { rem -= NTILE - ti; ti++; }
    int tj = ti + rem;
    bool offdiag = (ti != tj);

    int t = threadIdx.x;
    int w = t >> 5, l = t & 31;
    int r = w & 3;
    int g = w >> 2;

    __shared__ float  xi[3][32], xj[3][32];
    __shared__ float  mi_sm[32], mj_sm[32];
    __shared__ float  a_sm[32 * 32];
    __shared__ float2 SjP[8][16][32];
    __shared__ float  wred[8][4];
    __shared__ float  sW[XHIN * XHHID];
    __shared__ float  sB[XHHID];
    __shared__ float  hs[32][6];

    if (t < 32) {
        int rowg = b * NNODE + ti * 32 + t;
        xi[0][t] = xh[rowg * XHIN + 0];
        xi[1][t] = xh[rowg * XHIN + 1];
        xi[2][t] = xh[rowg * XHIN + 2];
        mi_sm[t] = node_mask[rowg];
    } else if (t < 64) {
        int tt = t - 32;
        int rowg = b * NNODE + tj * 32 + tt;
        xj[0][tt] = xh[rowg * XHIN + 0];
        xj[1][tt] = xh[rowg * XHIN + 1];
        xj[2][tt] = xh[rowg * XHIN + 2];
        mj_sm[tt] = node_mask[rowg];
    }

    if (!offdiag) {
        // full-batch masked reduction for mean/N (butterfly: all lanes hold sum)
        int rowg = b * NNODE + t;
        float m  = node_mask[rowg];
        float y0 = xh[rowg * XHIN + 0] * m;
        float y1 = xh[rowg * XHIN + 1] * m;
        float y2 = xh[rowg * XHIN + 2] * m;
        float y3 = m;
        #pragma unroll
        for (int off = 16; off > 0; off >>= 1) {
            y0 += __shfl_xor_sync(0xffffffffu, y0, off);
            y1 += __shfl_xor_sync(0xffffffffu, y1, off);
            y2 += __shfl_xor_sync(0xffffffffu, y2, off);
            y3 += __shfl_xor_sync(0xffffffffu, y3, off);
        }
        if (l == 0) { wred[w][0] = y0; wred[w][1] = y1; wred[w][2] = y2; wred[w][3] = y3; }

        // stage embedding weights + h rows for this 32-row tile
        for (int i = t; i < XHIN * XHHID; i += 256) sW[i] = W_xh[i];
        if (t < XHHID) sB[t] = b_xh[t];
        if (t < 192) {
            int rr = t / 6, cc = t % 6;
            hs[rr][cc] = xh[(size_t)(b * NNODE + ti * 32 + rr) * XHIN + 3 + cc];
        }
    }
    __syncthreads();

    if (!offdiag) {
        // per-thread combine (no extra barrier)
        float sx = 0.f, sy = 0.f, sz = 0.f, sn = 0.f;
        #pragma unroll
        for (int ww = 0; ww < 8; ww++) {
            sx += wred[ww][0]; sy += wred[ww][1];
            sz += wred[ww][2]; sn += wred[ww][3];
        }
        float mean0 = sx / sn, mean1 = sy / sn, mean2 = sz / sn;

        // xh embedding: 2048 outputs, 8 per thread, coalesced over o
        #pragma unroll
        for (int e = 0; e < 8; e++) {
            int v = e * 256 + t;
            int rr = v >> 6, o = v & 63;
            float mr  = mi_sm[rr];
            float xc0 = (xi[0][rr] - mean0) * mr;
            float xc1 = (xi[1][rr] - mean1) * mr;
            float xc2 = (xi[2][rr] - mean2) * mr;
            float acc = sB[o];
            acc = fmaf(xc0,       sW[0 * XHHID + o], acc);
            acc = fmaf(xc1,       sW[1 * XHHID + o], acc);
            acc = fmaf(xc2,       sW[2 * XHHID + o], acc);
            acc = fmaf(hs[rr][0], sW[3 * XHHID + o], acc);
            acc = fmaf(hs[rr][1], sW[4 * XHHID + o], acc);
            acc = fmaf(hs[rr][2], sW[5 * XHHID + o], acc);
            acc = fmaf(hs[rr][3], sW[6 * XHHID + o], acc);
            acc = fmaf(hs[rr][4], sW[7 * XHHID + o], acc);
            acc = fmaf(hs[rr][5], sW[8 * XHHID + o], acc);
            out[(size_t)(b * NNODE + ti * 32 + rr) * 256 + o] = acc * mr;
        }
    }

    // -- angles for the 32x32 tile (mean cancels in differences) -------------
    #pragma unroll
    for (int k = 0; k < 4; k++) {
        int q = t + k * 256;
        int i = q & 31, j = q >> 5;
        float dx = xi[0][i] - xj[0][j];
        float dy = xi[1][i] - xj[1][j];
        float dz = xi[2][i] - xj[2][j];
        float sq = fmaxf(fmaf(dx, dx, fmaf(dy, dy, dz * dz)), 0.0f);
        a_sm[j * 32 + i] = TWO_PI_F * sqrtf(sq + 1e-12f);
    }
    __syncthreads();

    const float c1 = 0.10381025296522944f;           // log2(100)/64
    float f = exp2f((float)(g * 32 + l) * c1);

    float mi[8];
    #pragma unroll
    for (int k = 0; k < 8; k++) mi[k] = mi_sm[r * 8 + k];

    float ssA[8], ccA[8];
    #pragma unroll
    for (int k = 0; k < 8; k++) { ssA[k] = 0.f; ccA[k] = 0.f; }

    for (int h = 0; h < 2; h++) {
        #pragma unroll 4
        for (int j2 = 0; j2 < 16; j2++) {
            int j = h * 16 + j2;
            float mj = mj_sm[j];
            const float4* ap = (const float4*)&a_sm[j * 32 + r * 8];
            float4 a0 = ap[0];
            float4 a1 = ap[1];
            float av[8] = {a0.x, a0.y, a0.z, a0.w, a1.x, a1.y, a1.z, a1.w};
            float sjs = 0.f, sjc = 0.f;
            #pragma unroll
            for (int k = 0; k < 8; k++) {
                float ang = av[k] * f;
                float s = __sinf(ang);
                float c = __cosf(ang);
                ssA[k] = fmaf(mj, s, ssA[k]);
                ccA[k] = fmaf(mj, c, ccA[k]);
                sjs    = fmaf(mi[k], s, sjs);
                sjc    = fmaf(mi[k], c, sjc);
            }
            if (offdiag) SjP[w][j2][l] = make_float2(sjs, sjc);
        }

        if (offdiag) {
            __syncthreads();
            #pragma unroll
            for (int k = 0; k < 4; k++) {
                int idx = t + k * 256;
                int gg  = idx >> 9;
                int jj  = (idx >> 5) & 15;
                int ll  = idx & 31;
                float2 v0 = SjP[gg * 4 + 0][jj][ll];
                float2 v1 = SjP[gg * 4 + 1][jj][ll];
                float2 v2 = SjP[gg * 4 + 2][jj][ll];
                float2 v3 = SjP[gg * 4 + 3][jj][ll];
                float ss = (v0.x + v1.x) + (v2.x + v3.x);
                float cc = (v0.y + v1.y) + (v2.y + v3.y);
                float* rp = &g_Spart[b][ti][tj * 32 + h * 16 + jj][0];
                rp[gg * 32 + ll]      = ss;
                rp[64 + gg * 32 + ll] = cc;
            }
            __syncthreads();
        }
    }

    float* basei = &g_Spart[b][tj][ti * 32][0];
    #pragma unroll
    for (int k = 0; k < 8; k++) {
        float* rp = basei + (r * 8 + k) * 128;
        rp[g * 32 + l]      = ssA[k];
        rp[64 + g * 32 + l] = ccA[k];
    }
}

// ---------------------------------------------------------------------------
// Epilogue: PURE projection GEMM, single barrier.
// grid = 128 row-groups (16 rows) x 3 col-slices (64 cols) = 384 blocks.
// Thread = (col c, row-quad rq): k-loop = LDS.128(S, broadcast) +
// LDS.32(W, conflict-free) + 4 FMA. S stored RAW pre-barrier in a float4-
// padded layout ([128][5] quads); mask/N scaling applied at the output
// (S-term gets mk^2/N, bias gets mk*256/N, matching the reference).
// N via butterfly reduce + post-barrier 8-word sum (no second barrier).
// grid = 384, block = 256, smem ~42KB
// ---------------------------------------------------------------------------
__global__ __launch_bounds__(256) void ep_gemm(
    const float* __restrict__ node_mask,
    const float* __restrict__ W_pos,
    const float* __restrict__ b_pos,
    float* __restrict__ out)
{
    int cb = blockIdx.x % 3;             // col slice: cols cb*64 .. cb*64+63
    int rg = blockIdx.x / 3;             // 0..127
    int b  = rg >> 4;
    int i0 = (rg & 15) << 4;             // 16 rows
    int t  = threadIdx.x;
    int w  = t >> 5, l = t & 31;

    __shared__ float  sWp[128 * 64];     // W_pos slice, 32 KB
    __shared__ float4 S4[128][5];        // raw S [k][row-quad], padded, 10 KB
    __shared__ float  wredN[8];

    // -- stage W slice: 8 independent LDG.128 per thread ---------------------
    {
        const float4* src = (const float4*)W_pos;   // 48 float4 per k-row
        float4*       dst = (float4*)sWp;           // 16 float4 per k-row
        #pragma unroll
        for (int ii = 0; ii < 8; ii++) {
            int idx = t + (ii << 8);                // 0..2047
            int kk = idx >> 4, c4 = idx & 15;
            dst[kk * 16 + c4] = src[kk * 48 + cb * 16 + c4];
        }
    }

    // -- slot sums -> raw S in smem (padded scatter) -------------------------
    {
        float* Ssc = (float*)S4;                    // row k = 20 floats
        #pragma unroll
        for (int ii = 0; ii < 8; ii++) {
            int v = t + (ii << 8);                  // 0..2047
            int rv = v >> 7, fv = v & 127;
            float s = 0.f;
            #pragma unroll
            for (int slot = 0; slot < NTILE; slot++)
                s += g_Spart[b][slot][i0 + rv][fv];
            Ssc[fv * 20 + rv] = s;
        }
    }

    // -- N reduction (butterfly; every lane holds warp sum) ------------------
    {
        float m = node_mask[b * NNODE + t];
        #pragma unroll
        for (int off = 16; off > 0; off >>= 1)
            m += __shfl_xor_sync(0xffffffffu, m, off);
        if (l == 0) wredN[w] = m;
    }
    __syncthreads();                                // the ONLY barrier

    float Ns = 0.f;
    #pragma unroll
    for (int ww = 0; ww < 8; ww++) Ns += wredN[ww];
    float sc0 = 1.0f / Ns;
    float sc1 = 256.0f / Ns;

    // -- matvec: thread = (col c, row-quad rq) -------------------------------
    int c  = t & 63;
    int rq = t >> 6;                                // rows i0+rq*4 .. +3
    float acc0 = 0.f, acc1 = 0.f, acc2 = 0.f, acc3 = 0.f;
    #pragma unroll 8
    for (int k = 0; k < 128; k++) {
        float4 sv = S4[k][rq];                      // broadcast LDS.128
        float  wv = sWp[k * 64 + c];                // conflict-free LDS.32
        acc0 = fmaf(sv.x, wv, acc0);
        acc1 = fmaf(sv.y, wv, acc1);
        acc2 = fmaf(sv.z, wv, acc2);
        acc3 = fmaf(sv.w, wv, acc3);
    }

    int col = cb * 64 + c;
    float bp = b_pos[col] * sc1;
    int rbase = b * NNODE + i0 + rq * 4;
    float m0 = node_mask[rbase + 0];
    float m1 = node_mask[rbase + 1];
    float m2 = node_mask[rbase + 2];
    float m3 = node_mask[rbase + 3];
    size_t obase = (size_t)rbase * 256 + 64 + col;
    out[obase]       = (acc0 * sc0 * m0 + bp) * m0;
    out[obase + 256] = (acc1 * sc0 * m1 + bp) * m1;
    out[obase + 512] = (acc2 * sc0 * m2 + bp) * m2;
    out[obase + 768] = (acc3 * sc0 * m3 + bp) * m3;
}

extern "C" void kernel_launch(void* const* d_in, const int* in_sizes, int n_in,
                              void* d_out, int out_size)
{
    // inputs (metadata order): t, xh, node_mask, edge_mask, W_xh, b_xh, W_pos, b_pos
    const float* xh        = (const float*)d_in[1];
    const float* node_mask = (const float*)d_in[2];
    const float* W_xh      = (const float*)d_in[4];
    const float* b_xh      = (const float*)d_in[5];
    const float* W_pos     = (const float*)d_in[6];
    const float* b_pos     = (const float*)d_in[7];
    float* out = (float*)d_out;

    pair_kernel<<<BATCH * NPAIR, 256>>>(xh, node_mask, W_xh, b_xh, out);
    ep_gemm<<<384, 256>>>(node_mask, W_pos, b_pos, out);
}